// round 1
// baseline (speedup 1.0000x reference)
#include <cuda_runtime.h>
#include <cstdint>

// Problem constants (from reference)
#define NB_CAT  8192
#define RANK    16
#define N_COLS  4
#define N_PAIRS 1048576

// out[p] = sum_c dot(cf[c, x[p,c], :], cf[c, y[p,c], :]) + (x==y ? std[c,x]^2 : 0)
//
// Cooperative layout per warp:
//   lane = 31..0
//   unit  = lane >> 2   (8 units/warp), each unit = one (pair, col)
//   sub   = lane & 3    (which float4 chunk of the 16-float row)
//   c     = unit & 3
//   psub  = unit >> 2   (pair 0/1 within this warp iteration)
// Each lane loads float4 of both the x-row and y-row at chunk `sub`,
// computes a partial 4-element dot, then xor-shuffle reduce:
//   xor 1,2  -> sum over the 4 chunks (full rank-16 dot per unit)
//   xor 4,8  -> sum over the 4 columns (stays within 16-lane pair half)
// Lanes 0 and 16 write out[p0], out[p1].

__device__ __forceinline__ int ldcg_i(const int* p) {
    int v;
    asm volatile("ld.global.cg.b32 %0, [%1];" : "=r"(v) : "l"(p));
    return v;
}

__global__ __launch_bounds__(256) void pair_cov_kernel(
    const int*   __restrict__ x,
    const int*   __restrict__ y,
    const float* __restrict__ cf,     // [N_COLS, NB_CAT, RANK]
    const float* __restrict__ stdv,   // [N_COLS, NB_CAT]
    float*       __restrict__ out,
    int n_pairs)
{
    const int lane = threadIdx.x & 31;
    const int sub  = lane & 3;        // float4 chunk within row
    const int unit = lane >> 2;       // 0..7
    const int c    = unit & 3;        // column
    const int psub = unit >> 2;       // pair within iteration (0/1)

    const int warp_global = (int)((blockIdx.x * blockDim.x + threadIdx.x) >> 5);
    const int nwarps      = (int)((gridDim.x * blockDim.x) >> 5);

    // per-column table bases
    const float4* cf_c  = (const float4*)(cf + (size_t)c * NB_CAT * RANK);
    const float*  std_c = stdv + (size_t)c * NB_CAT;

    for (int base = warp_global * 2; base < n_pairs; base += nwarps * 2) {
        const int p = base + psub;   // base even, n_pairs even -> p always < n_pairs

        // Coalesced index loads (streaming: bypass L1 to preserve table residency)
        const int xi = ldcg_i(x + (size_t)p * N_COLS + c);
        const int yi = ldcg_i(y + (size_t)p * N_COLS + c);

        // Row gathers: 4 lanes x float4 = one 64B row = one L1 wavefront each
        const float4 a = cf_c[(size_t)xi * (RANK / 4) + sub];
        const float4 b = cf_c[(size_t)yi * (RANK / 4) + sub];

        float part = a.x * b.x + a.y * b.y + a.z * b.z + a.w * b.w;

        // Diagonal term: added exactly once per unit (on sub==0 lane)
        if (sub == 0 && xi == yi) {
            const float s = std_c[xi];
            part += s * s;
        }

        // Reduce: chunks (xor 1,2) then columns (xor 4,8); bit4 (pair) preserved
        part += __shfl_xor_sync(0xffffffffu, part, 1);
        part += __shfl_xor_sync(0xffffffffu, part, 2);
        part += __shfl_xor_sync(0xffffffffu, part, 4);
        part += __shfl_xor_sync(0xffffffffu, part, 8);

        if (lane == 0 || lane == 16) {
            out[p] = part;
        }
    }
}

extern "C" void kernel_launch(void* const* d_in, const int* in_sizes, int n_in,
                              void* d_out, int out_size)
{
    const int*   x    = (const int*)d_in[0];
    const int*   y    = (const int*)d_in[1];
    const float* cf   = (const float*)d_in[2];
    const float* stdv = (const float*)d_in[3];
    float*       out  = (float*)d_out;

    const int n_pairs = out_size;  // 1048576

    // ~16 blocks/SM worth of warps, grid-stride over 512K warp-iterations
    const int threads = 256;
    const int blocks  = 148 * 16;
    pair_cov_kernel<<<blocks, threads>>>(x, y, cf, stdv, out, n_pairs);
}